// round 15
// baseline (speedup 1.0000x reference)
#include <cuda_runtime.h>
#include <cstdint>
#include <cfloat>
#include <math.h>

// Fixed problem shape (setup_inputs): N=8192, IN_F=512, OUT_F=64, C=2, k=32
#define N_     8192
#define INF_   512
#define OUTF_  64
#define C_     2
#define WCAP   64      // per-warp candidate capacity (>19 sigma at T0=2.42)
#define CAP    512     // 8 * WCAP
#define KMAX   64
#define T0     2.42f   // p=0.0078 -> m ~ 64 +/- 8; P(m<32) ~ 3e-5 per row

// Scratch for h = x @ W^T  [N_, OUTF_]  (2MB, device global: no allocations)
__device__ float g_h[N_ * OUTF_];

// ---------------------------------------------------------------------------
// Kernel 1: h = x @ W^T. Block = 64 rows x 64 f, 256 threads, 4x4 tile.
// float4 LDS both operands, stride 17 float4 padding (proven R14: 26us).
// ---------------------------------------------------------------------------
__global__ void __launch_bounds__(256) h_kernel(const float* __restrict__ x,
                                                const float* __restrict__ W) {
    __shared__ float4 x_s[64 * 17];   // [row][kk4] pad   17.4KB
    __shared__ float4 w_s[64 * 17];   // [f][kk4] pad     17.4KB
    const int t  = threadIdx.x;
    const int tx = t & 15;            // f lane: f = tx + 16*i
    const int ty = t >> 4;            // rows ty*4 .. ty*4+3
    const int rowBase = blockIdx.x * 64;

    const float4* x4 = (const float4*)x;   // row = 128 float4
    const float4* W4 = (const float4*)W;

    float acc[4][4];
#pragma unroll
    for (int j = 0; j < 4; j++)
#pragma unroll
        for (int i = 0; i < 4; i++) acc[j][i] = 0.f;

    for (int ch = 0; ch < 8; ch++) {   // 64-kk chunks (16 float4 each)
#pragma unroll
        for (int i = 0; i < 4; i++) {
            int idx = t + 256 * i;          // 0..1023
            int rr = idx >> 4, c4 = idx & 15;
            x_s[rr * 17 + c4] = x4[(long)(rowBase + rr) * 128 + ch * 16 + c4];
            w_s[rr * 17 + c4] = W4[(long)rr * 128 + ch * 16 + c4];  // rr = f
        }
        __syncthreads();

#pragma unroll 4
        for (int q = 0; q < 16; q++) {   // kk4 within chunk
            float4 xq[4], wq[4];
#pragma unroll
            for (int j = 0; j < 4; j++) xq[j] = x_s[(ty * 4 + j) * 17 + q];
#pragma unroll
            for (int i = 0; i < 4; i++) wq[i] = w_s[(tx + 16 * i) * 17 + q];
#pragma unroll
            for (int j = 0; j < 4; j++)
#pragma unroll
                for (int i = 0; i < 4; i++) {
                    acc[j][i] = fmaf(xq[j].x, wq[i].x, acc[j][i]);
                    acc[j][i] = fmaf(xq[j].y, wq[i].y, acc[j][i]);
                    acc[j][i] = fmaf(xq[j].z, wq[i].z, acc[j][i]);
                    acc[j][i] = fmaf(xq[j].w, wq[i].w, acc[j][i]);
                }
        }
        __syncthreads();
    }
#pragma unroll
    for (int j = 0; j < 4; j++)
#pragma unroll
        for (int i = 0; i < 4; i++)
            g_h[(long)(rowBase + ty * 4 + j) * OUTF_ + tx + 16 * i] = acc[j][i];
}

// ---------------------------------------------------------------------------
// Kernel 2 (fused): per attention row (16384 blocks, 256 threads).
// Zero-fill via cp.async.bulk (proven R13). T0=2.42 halves the candidate set
// (rank loop ~64 iters). Max phase deleted: sval[0] IS the row max; softmax
// weights computed after rank. Fallback (m<k or overflow) stays exact.
// ---------------------------------------------------------------------------
__global__ void __launch_bounds__(256) topk_kernel(const float* __restrict__ araw,
                                                   const int*   __restrict__ kptr,
                                                   float*       __restrict__ out,
                                                   float*       __restrict__ att) {
    __shared__ float4 z_s[256];      // 4KB of zeros (bulk-copy source)
    __shared__ float cvw[8][WCAP];
    __shared__ int   ciw[8][WCAP];
    __shared__ int   s_cw[8];
    __shared__ float cval[CAP];
    __shared__ int   cidx[CAP];
    __shared__ float sval[KMAX];     // rank-ordered raw values (sval[0] = max)
    __shared__ int   sidx[KMAX];
    __shared__ float sw[KMAX];
    __shared__ float s_bv[8];
    __shared__ int   s_bi[8];
    __shared__ float s_inv;
    __shared__ float s_lastV;
    __shared__ int   s_lastI;

    const int t    = threadIdx.x;
    const int lane = t & 31;
    const int wid  = t >> 5;
    const long r   = blockIdx.x;

    int k = 32;
    if (kptr) { k = *kptr; if (k < 1) k = 1; if (k > KMAX) k = KMAX; }

    z_s[t] = make_float4(0.f, 0.f, 0.f, 0.f);
    if (t < 8)    s_cw[t] = 0;
    if (t < KMAX) sw[t]   = 0.f;   // zero-pad for fixed-tree sum
    __syncthreads();

    // ---- offload att-row zero-fill to the async bulk engine ----
    if (att && t == 0) {
        asm volatile("fence.proxy.async;" ::: "memory");
        unsigned int saddr;
        asm("{ .reg .u64 tmp; cvta.to.shared.u64 tmp, %1; cvt.u32.u64 %0, tmp; }"
            : "=r"(saddr) : "l"((const void*)z_s));
        char* gdst = (char*)(att + r * (long)N_);
#pragma unroll
        for (int i = 0; i < 8; i++) {
            asm volatile(
                "cp.async.bulk.global.shared::cta.bulk_group [%0], [%1], %2;"
                :: "l"(gdst + i * 4096), "r"(saddr), "r"(4096) : "memory");
        }
        asm volatile("cp.async.bulk.commit_group;" ::: "memory");
    }

    // ---- stream: 4-batched loads (MLP=4), group-max-gated extraction ----
    const float4* src = (const float4*)(araw + r * (long)N_);

#define EXT(val, gi) do {                                                      \
        if ((val) >= T0) {                                                     \
            int p_ = atomicAdd(&s_cw[wid], 1);                                 \
            if (p_ < WCAP) { cvw[wid][p_] = (val); ciw[wid][p_] = (gi); }      \
        }                                                                      \
    } while (0)

#pragma unroll
    for (int g = 0; g < 2; g++) {
        float4 v[4];
#pragma unroll
        for (int i = 0; i < 4; i++)
            v[i] = __ldcs(src + t + 256 * (g * 4 + i));     // 4 in flight
#pragma unroll
        for (int i = 0; i < 4; i++) {
            float gm = fmaxf(fmaxf(v[i].x, v[i].y), fmaxf(v[i].z, v[i].w));
            if (gm >= T0) {   // ~3.1% of groups
                int b4 = 4 * (t + 256 * (g * 4 + i));
                EXT(v[i].x, b4);
                EXT(v[i].y, b4 + 1);
                EXT(v[i].z, b4 + 2);
                EXT(v[i].w, b4 + 3);
            }
        }
    }
#undef EXT
    __syncthreads();

    // ---- merge per-warp counts ----
    int cnts[8], offs[8], m = 0;
    bool ok = true;
#pragma unroll
    for (int j = 0; j < 8; j++) {
        cnts[j] = s_cw[j];
        offs[j] = m;
        m += cnts[j];
        ok = ok && (cnts[j] <= WCAP);
    }
    ok = ok && (m >= k);

    if (ok) {
        // compact per-warp lists into contiguous cval/cidx
#pragma unroll
        for (int j = 0; j < 8; j++)
            for (int i = t; i < cnts[j]; i += 256) {
                cval[offs[j] + i] = cvw[j][i];
                cidx[offs[j] + i] = ciw[j][i];
            }
        __syncthreads();

        // exact rank: value desc, index asc (jax tie-break); no expf here
        for (int i = t; i < m; i += 256) {
            float vi = cval[i];
            int   ii = cidx[i];
            int rank = 0;
            for (int j = 0; j < m; j++) {
                float vj = cval[j];
                rank += (vj > vi) || (vj == vi && cidx[j] < ii);
            }
            if (rank < k) { sval[rank] = vi; sidx[rank] = ii; }
        }
        __syncthreads();
    } else {
        // robust fallback: k deterministic arg-max passes over the global row
        if (t == 0) { s_lastV = FLT_MAX; s_lastI = -1; }
        __syncthreads();
        const float* rowg = araw + r * (long)N_;
        for (int p = 0; p < k; p++) {
            float lastV = s_lastV; int lastI = s_lastI;
            float bv = -FLT_MAX; int bi = N_;
            for (int e = t; e < N_; e += 256) {
                float vv = rowg[e];
                bool after = (vv < lastV) || (vv == lastV && e > lastI);
                if (after && ((vv > bv) || (vv == bv && e < bi))) { bv = vv; bi = e; }
            }
#pragma unroll
            for (int o = 16; o > 0; o >>= 1) {
                float ov = __shfl_xor_sync(0xffffffffu, bv, o);
                int   oi = __shfl_xor_sync(0xffffffffu, bi, o);
                if ((ov > bv) || (ov == bv && oi < bi)) { bv = ov; bi = oi; }
            }
            if (lane == 0) { s_bv[wid] = bv; s_bi[wid] = bi; }
            __syncthreads();
            if (t == 0) {
                float gv = s_bv[0]; int gi = s_bi[0];
#pragma unroll
                for (int j = 1; j < 8; j++) {
                    if ((s_bv[j] > gv) || (s_bv[j] == gv && s_bi[j] < gi)) { gv = s_bv[j]; gi = s_bi[j]; }
                }
                sval[p] = gv; sidx[p] = gi;
                s_lastV = gv; s_lastI = gi;
            }
            __syncthreads();
        }
    }

    // ---- softmax weights: M = sval[0] (exact row max, rank 0) ----
    if (t < k) sw[t] = expf(sval[t] - sval[0]);
    __syncthreads();

    // deterministic denominator: fixed warp-0 shuffle tree
    if (wid == 0) {
        float s = sw[lane] + sw[lane + 32];
#pragma unroll
        for (int o = 16; o > 0; o >>= 1)
            s += __shfl_xor_sync(0xffffffffu, s, o);
        if (lane == 0) s_inv = 1.0f / s;
    }

    // ---- bulk zeros must land before the scatter ----
    if (att && t == 0)
        asm volatile("cp.async.bulk.wait_group 0;" ::: "memory");
    __syncthreads();
    const float inv = s_inv;

    // ---- scatter the k softmax values over the zeroed row ----
    if (att && t < k) att[r * (long)N_ + sidx[t]] = sw[t] * inv;

    // ---- h_prime row -> concat-transposed output [n, c*OUTF + f] ----
    if (out && t < OUTF_) {
        float acc = 0.f;
        for (int p = 0; p < k; p++)
            acc = fmaf(sw[p] * inv, g_h[(long)sidx[p] * OUTF_ + t], acc);
        const int c = (int)(r / N_);
        const int n = (int)(r % N_);
        out[(long)n * (C_ * OUTF_) + c * OUTF_ + t] = acc;
    }
}

// ---------------------------------------------------------------------------
extern "C" void kernel_launch(void* const* d_in, const int* in_sizes, int n_in,
                              void* d_out, int out_size) {
    const float* x    = (const float*)d_in[0];
    const float* W    = (const float*)d_in[1];
    const float* araw = (const float*)d_in[2];
    const int*   kptr = (n_in > 3) ? (const int*)d_in[3] : nullptr;

    const long attElems = (long)in_sizes[2];        // R * N
    const int  R        = (int)(attElems / N_);     // 16384
    const long outElems = (long)N_ * C_ * OUTF_;    // 1,048,576

    float* outp = nullptr;
    float* attp = nullptr;
    const long osz = (long)out_size;
    if (osz >= outElems + attElems) {
        outp = (float*)d_out;
        attp = (float*)d_out + outElems;   // tuple order: (out, att)
    } else if (osz == attElems) {
        attp = (float*)d_out;
    } else {
        outp = (float*)d_out;
    }

    if (outp) h_kernel<<<N_ / 64, 256>>>(x, W);
    topk_kernel<<<R, 256>>>(araw, kptr, outp, attp);
}

// round 16
// speedup vs baseline: 1.2113x; 1.2113x over previous
#include <cuda_runtime.h>
#include <cstdint>
#include <cfloat>
#include <math.h>

// Fixed problem shape (setup_inputs): N=8192, IN_F=512, OUT_F=64, C=2, k=32
#define N_     8192
#define INF_   512
#define OUTF_  64
#define C_     2
#define WCAP   64      // per-warp candidate capacity (10 sigma at T0=2.2)
#define CAP    512     // 8 * WCAP
#define KMAX   64
#define T0     2.2f    // m ~ 114 +/- 11; P(m<32) ~ 1e-20 per row (proven safe)

// Scratch for h = x @ W^T  [N_, OUTF_]  (2MB, device global: no allocations)
__device__ float g_h[N_ * OUTF_];

// ---------------------------------------------------------------------------
// Kernel 1: h = x @ W^T. Block = 64 rows x 64 f, 256 threads, 4x4 tile.
// float4 LDS both operands, stride 17 float4 padding (proven R14: 26us).
// ---------------------------------------------------------------------------
__global__ void __launch_bounds__(256) h_kernel(const float* __restrict__ x,
                                                const float* __restrict__ W) {
    __shared__ float4 x_s[64 * 17];   // [row][kk4] pad   17.4KB
    __shared__ float4 w_s[64 * 17];   // [f][kk4] pad     17.4KB
    const int t  = threadIdx.x;
    const int tx = t & 15;            // f lane: f = tx + 16*i
    const int ty = t >> 4;            // rows ty*4 .. ty*4+3
    const int rowBase = blockIdx.x * 64;

    const float4* x4 = (const float4*)x;   // row = 128 float4
    const float4* W4 = (const float4*)W;

    float acc[4][4];
#pragma unroll
    for (int j = 0; j < 4; j++)
#pragma unroll
        for (int i = 0; i < 4; i++) acc[j][i] = 0.f;

    for (int ch = 0; ch < 8; ch++) {   // 64-kk chunks (16 float4 each)
#pragma unroll
        for (int i = 0; i < 4; i++) {
            int idx = t + 256 * i;          // 0..1023
            int rr = idx >> 4, c4 = idx & 15;
            x_s[rr * 17 + c4] = x4[(long)(rowBase + rr) * 128 + ch * 16 + c4];
            w_s[rr * 17 + c4] = W4[(long)rr * 128 + ch * 16 + c4];  // rr = f
        }
        __syncthreads();

#pragma unroll 4
        for (int q = 0; q < 16; q++) {   // kk4 within chunk
            float4 xq[4], wq[4];
#pragma unroll
            for (int j = 0; j < 4; j++) xq[j] = x_s[(ty * 4 + j) * 17 + q];
#pragma unroll
            for (int i = 0; i < 4; i++) wq[i] = w_s[(tx + 16 * i) * 17 + q];
#pragma unroll
            for (int j = 0; j < 4; j++)
#pragma unroll
                for (int i = 0; i < 4; i++) {
                    acc[j][i] = fmaf(xq[j].x, wq[i].x, acc[j][i]);
                    acc[j][i] = fmaf(xq[j].y, wq[i].y, acc[j][i]);
                    acc[j][i] = fmaf(xq[j].z, wq[i].z, acc[j][i]);
                    acc[j][i] = fmaf(xq[j].w, wq[i].w, acc[j][i]);
                }
        }
        __syncthreads();
    }
#pragma unroll
    for (int j = 0; j < 4; j++)
#pragma unroll
        for (int i = 0; i < 4; i++)
            g_h[(long)(rowBase + ty * 4 + j) * OUTF_ + tx + 16 * i] = acc[j][i];
}

// ---------------------------------------------------------------------------
// Kernel 2 (fused): per attention row (16384 blocks, 256 threads).
// Zero-fill via cp.async.bulk (proven R13). T0=2.2 (proven: no fallback).
// Rank: 2-way j-split (thread t&127 ranks candidate i over half the j range,
// partials combined in smem) -> critical path halved. sval[0] = row max.
// ---------------------------------------------------------------------------
__global__ void __launch_bounds__(256) topk_kernel(const float* __restrict__ araw,
                                                   const int*   __restrict__ kptr,
                                                   float*       __restrict__ out,
                                                   float*       __restrict__ att) {
    __shared__ float4 z_s[256];      // 4KB of zeros (bulk-copy source)
    __shared__ float cvw[8][WCAP];
    __shared__ int   ciw[8][WCAP];
    __shared__ int   s_cw[8];
    __shared__ float cval[CAP];
    __shared__ int   cidx[CAP];
    __shared__ int   p0[CAP];        // partial ranks, j-half 0
    __shared__ int   p1[CAP];        // partial ranks, j-half 1
    __shared__ float sval[KMAX];     // rank-ordered raw values (sval[0] = max)
    __shared__ int   sidx[KMAX];
    __shared__ float sw[KMAX];
    __shared__ float s_bv[8];
    __shared__ int   s_bi[8];
    __shared__ float s_inv;
    __shared__ float s_lastV;
    __shared__ int   s_lastI;

    const int t    = threadIdx.x;
    const int lane = t & 31;
    const int wid  = t >> 5;
    const long r   = blockIdx.x;

    int k = 32;
    if (kptr) { k = *kptr; if (k < 1) k = 1; if (k > KMAX) k = KMAX; }

    z_s[t] = make_float4(0.f, 0.f, 0.f, 0.f);
    if (t < 8)    s_cw[t] = 0;
    if (t < KMAX) sw[t]   = 0.f;   // zero-pad for fixed-tree sum
    __syncthreads();

    // ---- offload att-row zero-fill to the async bulk engine ----
    if (att && t == 0) {
        asm volatile("fence.proxy.async;" ::: "memory");
        unsigned int saddr;
        asm("{ .reg .u64 tmp; cvta.to.shared.u64 tmp, %1; cvt.u32.u64 %0, tmp; }"
            : "=r"(saddr) : "l"((const void*)z_s));
        char* gdst = (char*)(att + r * (long)N_);
#pragma unroll
        for (int i = 0; i < 8; i++) {
            asm volatile(
                "cp.async.bulk.global.shared::cta.bulk_group [%0], [%1], %2;"
                :: "l"(gdst + i * 4096), "r"(saddr), "r"(4096) : "memory");
        }
        asm volatile("cp.async.bulk.commit_group;" ::: "memory");
    }

    // ---- stream: 4-batched loads (MLP=4), group-max-gated extraction ----
    const float4* src = (const float4*)(araw + r * (long)N_);

#define EXT(val, gi) do {                                                      \
        if ((val) >= T0) {                                                     \
            int p_ = atomicAdd(&s_cw[wid], 1);                                 \
            if (p_ < WCAP) { cvw[wid][p_] = (val); ciw[wid][p_] = (gi); }      \
        }                                                                      \
    } while (0)

#pragma unroll
    for (int g = 0; g < 2; g++) {
        float4 v[4];
#pragma unroll
        for (int i = 0; i < 4; i++)
            v[i] = __ldcs(src + t + 256 * (g * 4 + i));     // 4 in flight
#pragma unroll
        for (int i = 0; i < 4; i++) {
            float gm = fmaxf(fmaxf(v[i].x, v[i].y), fmaxf(v[i].z, v[i].w));
            if (gm >= T0) {   // ~5.4% of groups
                int b4 = 4 * (t + 256 * (g * 4 + i));
                EXT(v[i].x, b4);
                EXT(v[i].y, b4 + 1);
                EXT(v[i].z, b4 + 2);
                EXT(v[i].w, b4 + 3);
            }
        }
    }
#undef EXT
    __syncthreads();

    // ---- merge per-warp counts ----
    int cnts[8], offs[8], m = 0;
    bool ok = true;
#pragma unroll
    for (int j = 0; j < 8; j++) {
        cnts[j] = s_cw[j];
        offs[j] = m;
        m += cnts[j];
        ok = ok && (cnts[j] <= WCAP);
    }
    ok = ok && (m >= k);

    if (ok) {
        // compact per-warp lists into contiguous cval/cidx
#pragma unroll
        for (int j = 0; j < 8; j++)
            for (int i = t; i < cnts[j]; i += 256) {
                cval[offs[j] + i] = cvw[j][i];
                cidx[offs[j] + i] = ciw[j][i];
            }
        __syncthreads();

        // exact rank (value desc, index asc), 2-way j-split:
        // thread t&127 handles candidates i = (t&127) + 128*s over the
        // j-half selected by t>>7; partials combined after a barrier.
        const int tPair = t & 127;
        const int half  = t >> 7;
        const int mh    = m >> 1;
        const int jb    = half ? mh : 0;
        const int je    = half ? m  : mh;
        for (int i = tPair; i < m; i += 128) {
            float vi = cval[i];
            int   ii = cidx[i];
            int cnt = 0;
            for (int j = jb; j < je; j++) {
                float vj = cval[j];
                cnt += (vj > vi) || (vj == vi && cidx[j] < ii);
            }
            (half ? p1 : p0)[i] = cnt;
        }
        __syncthreads();
        for (int i = t; i < m; i += 256) {
            int rank = p0[i] + p1[i];
            if (rank < k) { sval[rank] = cval[i]; sidx[rank] = cidx[i]; }
        }
        __syncthreads();
    } else {
        // robust fallback: k deterministic arg-max passes over the global row
        if (t == 0) { s_lastV = FLT_MAX; s_lastI = -1; }
        __syncthreads();
        const float* rowg = araw + r * (long)N_;
        for (int p = 0; p < k; p++) {
            float lastV = s_lastV; int lastI = s_lastI;
            float bv = -FLT_MAX; int bi = N_;
            for (int e = t; e < N_; e += 256) {
                float vv = rowg[e];
                bool after = (vv < lastV) || (vv == lastV && e > lastI);
                if (after && ((vv > bv) || (vv == bv && e < bi))) { bv = vv; bi = e; }
            }
#pragma unroll
            for (int o = 16; o > 0; o >>= 1) {
                float ov = __shfl_xor_sync(0xffffffffu, bv, o);
                int   oi = __shfl_xor_sync(0xffffffffu, bi, o);
                if ((ov > bv) || (ov == bv && oi < bi)) { bv = ov; bi = oi; }
            }
            if (lane == 0) { s_bv[wid] = bv; s_bi[wid] = bi; }
            __syncthreads();
            if (t == 0) {
                float gv = s_bv[0]; int gi = s_bi[0];
#pragma unroll
                for (int j = 1; j < 8; j++) {
                    if ((s_bv[j] > gv) || (s_bv[j] == gv && s_bi[j] < gi)) { gv = s_bv[j]; gi = s_bi[j]; }
                }
                sval[p] = gv; sidx[p] = gi;
                s_lastV = gv; s_lastI = gi;
            }
            __syncthreads();
        }
    }

    // ---- softmax weights: M = sval[0] (exact row max, rank 0) ----
    if (t < k) sw[t] = expf(sval[t] - sval[0]);
    __syncthreads();

    // deterministic denominator: fixed warp-0 shuffle tree
    if (wid == 0) {
        float s = sw[lane] + sw[lane + 32];
#pragma unroll
        for (int o = 16; o > 0; o >>= 1)
            s += __shfl_xor_sync(0xffffffffu, s, o);
        if (lane == 0) s_inv = 1.0f / s;
    }

    // ---- bulk zeros must land before the scatter ----
    if (att && t == 0)
        asm volatile("cp.async.bulk.wait_group 0;" ::: "memory");
    __syncthreads();
    const float inv = s_inv;

    // ---- scatter the k softmax values over the zeroed row ----
    if (att && t < k) att[r * (long)N_ + sidx[t]] = sw[t] * inv;

    // ---- h_prime row -> concat-transposed output [n, c*OUTF + f] ----
    if (out && t < OUTF_) {
        float acc = 0.f;
        for (int p = 0; p < k; p++)
            acc = fmaf(sw[p] * inv, g_h[(long)sidx[p] * OUTF_ + t], acc);
        const int c = (int)(r / N_);
        const int n = (int)(r % N_);
        out[(long)n * (C_ * OUTF_) + c * OUTF_ + t] = acc;
    }
}

// ---------------------------------------------------------------------------
extern "C" void kernel_launch(void* const* d_in, const int* in_sizes, int n_in,
                              void* d_out, int out_size) {
    const float* x    = (const float*)d_in[0];
    const float* W    = (const float*)d_in[1];
    const float* araw = (const float*)d_in[2];
    const int*   kptr = (n_in > 3) ? (const int*)d_in[3] : nullptr;

    const long attElems = (long)in_sizes[2];        // R * N
    const int  R        = (int)(attElems / N_);     // 16384
    const long outElems = (long)N_ * C_ * OUTF_;    // 1,048,576

    float* outp = nullptr;
    float* attp = nullptr;
    const long osz = (long)out_size;
    if (osz >= outElems + attElems) {
        outp = (float*)d_out;
        attp = (float*)d_out + outElems;   // tuple order: (out, att)
    } else if (osz == attElems) {
        attp = (float*)d_out;
    } else {
        outp = (float*)d_out;
    }

    if (outp) h_kernel<<<N_ / 64, 256>>>(x, W);
    topk_kernel<<<R, 256>>>(araw, kptr, outp, attp);
}

// round 17
// speedup vs baseline: 1.4006x; 1.1563x over previous
#include <cuda_runtime.h>
#include <cstdint>
#include <cfloat>
#include <math.h>

// Fixed problem shape (setup_inputs): N=8192, IN_F=512, OUT_F=64, C=2, k=32
#define N_     8192
#define INF_   512
#define OUTF_  64
#define C_     2
#define WCAP   64      // per-warp candidate capacity (10 sigma at T0=2.2)
#define CAP    512     // 8 * WCAP
#define KMAX   64
#define T0     2.2f    // m ~ 114 +/- 11; P(m<32) ~ 1e-20 per row (proven safe)

// Scratch for h = x @ W^T  [N_, OUTF_]  (2MB, device global: no allocations)
__device__ float g_h[N_ * OUTF_];

__device__ __forceinline__ unsigned long long fma2(unsigned long long a,
                                                   unsigned long long b,
                                                   unsigned long long c) {
    unsigned long long d;
    asm("fma.rn.f32x2 %0, %1, %2, %3;" : "=l"(d) : "l"(a), "l"(b), "l"(c));
    return d;
}

// ---------------------------------------------------------------------------
// Kernel 1: h = x @ W^T. Block = 64 rows x 64 f, 256 threads, 4x4 tile.
// float4 LDS both operands (stride-17-float4 pad, proven R14), inner math in
// packed fma.rn.f32x2: LDS.128 lands (x0,x1)(x2,x3) in consecutive reg pairs,
// consumed directly as u64 lanes -> FFMA instruction count halved.
// ---------------------------------------------------------------------------
__global__ void __launch_bounds__(256) h_kernel(const float* __restrict__ x,
                                                const float* __restrict__ W) {
    __shared__ float4 x_s[64 * 17];   // [row][kk4] pad   17.4KB
    __shared__ float4 w_s[64 * 17];   // [f][kk4] pad     17.4KB
    const int t  = threadIdx.x;
    const int tx = t & 15;            // f lane: f = tx + 16*i
    const int ty = t >> 4;            // rows ty*4 .. ty*4+3
    const int rowBase = blockIdx.x * 64;

    const float4* x4 = (const float4*)x;   // row = 128 float4
    const float4* W4 = (const float4*)W;

    unsigned long long acc[4][4];     // (even,odd) partial sums per output
#pragma unroll
    for (int j = 0; j < 4; j++)
#pragma unroll
        for (int i = 0; i < 4; i++) acc[j][i] = 0ull;

    for (int ch = 0; ch < 8; ch++) {   // 64-kk chunks (16 float4 each)
#pragma unroll
        for (int i = 0; i < 4; i++) {
            int idx = t + 256 * i;          // 0..1023
            int rr = idx >> 4, c4 = idx & 15;
            x_s[rr * 17 + c4] = x4[(long)(rowBase + rr) * 128 + ch * 16 + c4];
            w_s[rr * 17 + c4] = W4[(long)rr * 128 + ch * 16 + c4];  // rr = f
        }
        __syncthreads();

#pragma unroll 4
        for (int q = 0; q < 16; q++) {   // kk4 within chunk
            ulonglong2 xq[4], wq[4];
#pragma unroll
            for (int j = 0; j < 4; j++)
                xq[j] = *(const ulonglong2*)&x_s[(ty * 4 + j) * 17 + q];
#pragma unroll
            for (int i = 0; i < 4; i++)
                wq[i] = *(const ulonglong2*)&w_s[(tx + 16 * i) * 17 + q];
#pragma unroll
            for (int j = 0; j < 4; j++)
#pragma unroll
                for (int i = 0; i < 4; i++) {
                    acc[j][i] = fma2(xq[j].x, wq[i].x, acc[j][i]);
                    acc[j][i] = fma2(xq[j].y, wq[i].y, acc[j][i]);
                }
        }
        __syncthreads();
    }
#pragma unroll
    for (int j = 0; j < 4; j++)
#pragma unroll
        for (int i = 0; i < 4; i++) {
            float lo = __uint_as_float((unsigned)(acc[j][i] & 0xffffffffu));
            float hi = __uint_as_float((unsigned)(acc[j][i] >> 32));
            g_h[(long)(rowBase + ty * 4 + j) * OUTF_ + tx + 16 * i] = lo + hi;
        }
}

// ---------------------------------------------------------------------------
// Kernel 2 (fused): per attention row (16384 blocks, 256 threads).
// Zero-fill via cp.async.bulk (R13). T0=2.2 (proven: no fallback).
// Rank: 2-way j-split with TIE-FREE hot loop — count greater + equal only
// (1 LDS/j); index tie-break runs only if an actual tie exists (never, for
// continuous data, but exactness preserved). sval[0] = row max.
// ---------------------------------------------------------------------------
__global__ void __launch_bounds__(256) topk_kernel(const float* __restrict__ araw,
                                                   const int*   __restrict__ kptr,
                                                   float*       __restrict__ out,
                                                   float*       __restrict__ att) {
    __shared__ float4 z_s[256];      // 4KB of zeros (bulk-copy source)
    __shared__ float cvw[8][WCAP];
    __shared__ int   ciw[8][WCAP];
    __shared__ int   s_cw[8];
    __shared__ float cval[CAP];
    __shared__ int   cidx[CAP];
    __shared__ int   p0[CAP];        // packed partials (cg<<10)|ce, j-half 0
    __shared__ int   p1[CAP];        // packed partials (cg<<10)|ce, j-half 1
    __shared__ float sval[KMAX];     // rank-ordered raw values (sval[0] = max)
    __shared__ int   sidx[KMAX];
    __shared__ float sw[KMAX];
    __shared__ float s_bv[8];
    __shared__ int   s_bi[8];
    __shared__ float s_inv;
    __shared__ float s_lastV;
    __shared__ int   s_lastI;

    const int t    = threadIdx.x;
    const int lane = t & 31;
    const int wid  = t >> 5;
    const long r   = blockIdx.x;

    int k = 32;
    if (kptr) { k = *kptr; if (k < 1) k = 1; if (k > KMAX) k = KMAX; }

    z_s[t] = make_float4(0.f, 0.f, 0.f, 0.f);
    if (t < 8)    s_cw[t] = 0;
    if (t < KMAX) sw[t]   = 0.f;   // zero-pad for fixed-tree sum
    __syncthreads();

    // ---- offload att-row zero-fill to the async bulk engine ----
    if (att && t == 0) {
        asm volatile("fence.proxy.async;" ::: "memory");
        unsigned int saddr;
        asm("{ .reg .u64 tmp; cvta.to.shared.u64 tmp, %1; cvt.u32.u64 %0, tmp; }"
            : "=r"(saddr) : "l"((const void*)z_s));
        char* gdst = (char*)(att + r * (long)N_);
#pragma unroll
        for (int i = 0; i < 8; i++) {
            asm volatile(
                "cp.async.bulk.global.shared::cta.bulk_group [%0], [%1], %2;"
                :: "l"(gdst + i * 4096), "r"(saddr), "r"(4096) : "memory");
        }
        asm volatile("cp.async.bulk.commit_group;" ::: "memory");
    }

    // ---- stream: 4-batched loads (MLP=4), group-max-gated extraction ----
    const float4* src = (const float4*)(araw + r * (long)N_);

#define EXT(val, gi) do {                                                      \
        if ((val) >= T0) {                                                     \
            int p_ = atomicAdd(&s_cw[wid], 1);                                 \
            if (p_ < WCAP) { cvw[wid][p_] = (val); ciw[wid][p_] = (gi); }      \
        }                                                                      \
    } while (0)

#pragma unroll
    for (int g = 0; g < 2; g++) {
        float4 v[4];
#pragma unroll
        for (int i = 0; i < 4; i++)
            v[i] = __ldcs(src + t + 256 * (g * 4 + i));     // 4 in flight
#pragma unroll
        for (int i = 0; i < 4; i++) {
            float gm = fmaxf(fmaxf(v[i].x, v[i].y), fmaxf(v[i].z, v[i].w));
            if (gm >= T0) {   // ~5.4% of groups
                int b4 = 4 * (t + 256 * (g * 4 + i));
                EXT(v[i].x, b4);
                EXT(v[i].y, b4 + 1);
                EXT(v[i].z, b4 + 2);
                EXT(v[i].w, b4 + 3);
            }
        }
    }
#undef EXT
    __syncthreads();

    // ---- merge per-warp counts ----
    int cnts[8], offs[8], m = 0;
    bool ok = true;
#pragma unroll
    for (int j = 0; j < 8; j++) {
        cnts[j] = s_cw[j];
        offs[j] = m;
        m += cnts[j];
        ok = ok && (cnts[j] <= WCAP);
    }
    ok = ok && (m >= k);

    if (ok) {
        // compact per-warp lists into contiguous cval/cidx
#pragma unroll
        for (int j = 0; j < 8; j++)
            for (int i = t; i < cnts[j]; i += 256) {
                cval[offs[j] + i] = cvw[j][i];
                cidx[offs[j] + i] = ciw[j][i];
            }
        __syncthreads();

        // tie-free rank partials (value only), 2-way j-split
        const int tPair = t & 127;
        const int half  = t >> 7;
        const int mh    = m >> 1;
        const int jb    = half ? mh : 0;
        const int je    = half ? m  : mh;
        for (int i = tPair; i < m; i += 128) {
            float vi = cval[i];
            int cg = 0, ce = 0;
            for (int j = jb; j < je; j++) {
                float vj = cval[j];
                cg += (vj > vi);
                ce += (vj == vi);
            }
            (half ? p1 : p0)[i] = (cg << 10) | ce;
        }
        __syncthreads();
        for (int i = t; i < m; i += 256) {
            int tot = p0[i] + p1[i];
            int rank = tot >> 10;
            int ce   = tot & 1023;     // includes self
            if (ce != 1) {             // actual tie (never for continuous data)
                float vi = cval[i];
                int   ii = cidx[i];
                for (int j = 0; j < m; j++)
                    rank += (cval[j] == vi && cidx[j] < ii);
            }
            if (rank < k) { sval[rank] = cval[i]; sidx[rank] = cidx[i]; }
        }
        __syncthreads();
    } else {
        // robust fallback: k deterministic arg-max passes over the global row
        if (t == 0) { s_lastV = FLT_MAX; s_lastI = -1; }
        __syncthreads();
        const float* rowg = araw + r * (long)N_;
        for (int p = 0; p < k; p++) {
            float lastV = s_lastV; int lastI = s_lastI;
            float bv = -FLT_MAX; int bi = N_;
            for (int e = t; e < N_; e += 256) {
                float vv = rowg[e];
                bool after = (vv < lastV) || (vv == lastV && e > lastI);
                if (after && ((vv > bv) || (vv == bv && e < bi))) { bv = vv; bi = e; }
            }
#pragma unroll
            for (int o = 16; o > 0; o >>= 1) {
                float ov = __shfl_xor_sync(0xffffffffu, bv, o);
                int   oi = __shfl_xor_sync(0xffffffffu, bi, o);
                if ((ov > bv) || (ov == bv && oi < bi)) { bv = ov; bi = oi; }
            }
            if (lane == 0) { s_bv[wid] = bv; s_bi[wid] = bi; }
            __syncthreads();
            if (t == 0) {
                float gv = s_bv[0]; int gi = s_bi[0];
#pragma unroll
                for (int j = 1; j < 8; j++) {
                    if ((s_bv[j] > gv) || (s_bv[j] == gv && s_bi[j] < gi)) { gv = s_bv[j]; gi = s_bi[j]; }
                }
                sval[p] = gv; sidx[p] = gi;
                s_lastV = gv; s_lastI = gi;
            }
            __syncthreads();
        }
    }

    // ---- softmax weights: M = sval[0] (exact row max, rank 0) ----
    if (t < k) sw[t] = expf(sval[t] - sval[0]);
    __syncthreads();

    // deterministic denominator: fixed warp-0 shuffle tree
    if (wid == 0) {
        float s = sw[lane] + sw[lane + 32];
#pragma unroll
        for (int o = 16; o > 0; o >>= 1)
            s += __shfl_xor_sync(0xffffffffu, s, o);
        if (lane == 0) s_inv = 1.0f / s;
    }

    // ---- bulk zeros must land before the scatter ----
    if (att && t == 0)
        asm volatile("cp.async.bulk.wait_group 0;" ::: "memory");
    __syncthreads();
    const float inv = s_inv;

    // ---- scatter the k softmax values over the zeroed row ----
    if (att && t < k) att[r * (long)N_ + sidx[t]] = sw[t] * inv;

    // ---- h_prime row -> concat-transposed output [n, c*OUTF + f] ----
    if (out && t < OUTF_) {
        float acc = 0.f;
        for (int p = 0; p < k; p++)
            acc = fmaf(sw[p] * inv, g_h[(long)sidx[p] * OUTF_ + t], acc);
        const int c = (int)(r / N_);
        const int n = (int)(r % N_);
        out[(long)n * (C_ * OUTF_) + c * OUTF_ + t] = acc;
    }
}

// ---------------------------------------------------------------------------
extern "C" void kernel_launch(void* const* d_in, const int* in_sizes, int n_in,
                              void* d_out, int out_size) {
    const float* x    = (const float*)d_in[0];
    const float* W    = (const float*)d_in[1];
    const float* araw = (const float*)d_in[2];
    const int*   kptr = (n_in > 3) ? (const int*)d_in[3] : nullptr;

    const long attElems = (long)in_sizes[2];        // R * N
    const int  R        = (int)(attElems / N_);     // 16384
    const long outElems = (long)N_ * C_ * OUTF_;    // 1,048,576

    float* outp = nullptr;
    float* attp = nullptr;
    const long osz = (long)out_size;
    if (osz >= outElems + attElems) {
        outp = (float*)d_out;
        attp = (float*)d_out + outElems;   // tuple order: (out, att)
    } else if (osz == attElems) {
        attp = (float*)d_out;
    } else {
        outp = (float*)d_out;
    }

    if (outp) h_kernel<<<N_ / 64, 256>>>(x, W);
    topk_kernel<<<R, 256>>>(araw, kptr, outp, attp);
}